// round 12
// baseline (speedup 1.0000x reference)
#include <cuda_runtime.h>
#include <cuda_bf16.h>
#include <cstdint>

#define B_  512
#define T_  512
#define F_  128
#define NU  50
#define NC  150   // 3*NU
#define XP  160   // padded X row (floats)

// Scratch for projected inputs X[b][t][160].
__device__ float g_X[(size_t)B_ * T_ * XP];

typedef unsigned long long ull;

__device__ __forceinline__ float sigm(float x) {
    return __fdividef(1.f, 1.f + __expf(-x));
}
__device__ __forceinline__ float tanh_fast(float x) {
    return __fdividef(2.f, 1.f + __expf(-2.f * x)) - 1.f;
}
__device__ __forceinline__ uint32_t smem_u32(const void* p) {
    uint32_t a;
    asm("{ .reg .u64 t; cvta.to.shared.u64 t, %1; cvt.u32.u64 %0, t; }"
        : "=r"(a) : "l"(p));
    return a;
}

// ================= Kernel 1: xproj via HMMA, N split x2, M split x2 =========
#define TM   128
#define TNH  80                          // N per CTA
#define TK   128
#define LDAB 136                         // bf16 stride (272B, ldmatrix-friendly)

#define SX_BIAS 0                                   // 160 floats (global cols)
#define SX_BH   1024                                // 80*136*2 = 21760
#define SX_BL   (SX_BH + TNH * LDAB * 2)
#define SX_AH   (SX_BL + TNH * LDAB * 2)
#define SX_AL   (SX_AH + TM * LDAB * 2)
#define SX_TOT  (SX_AL + TM * LDAB * 2)             // 114176 (~111.5KB)

__device__ __forceinline__ void ldmx4(uint32_t* r, uint32_t addr) {
    asm volatile("ldmatrix.sync.aligned.m8n8.x4.shared.b16 {%0,%1,%2,%3}, [%4];"
                 : "=r"(r[0]), "=r"(r[1]), "=r"(r[2]), "=r"(r[3]) : "r"(addr));
}
__device__ __forceinline__ void mma16816(float* c, const uint32_t* a,
                                         uint32_t b0, uint32_t b1) {
    asm volatile(
        "mma.sync.aligned.m16n8k16.row.col.f32.bf16.bf16.f32 "
        "{%0,%1,%2,%3}, {%4,%5,%6,%7}, {%8,%9}, {%0,%1,%2,%3};"
        : "+f"(c[0]), "+f"(c[1]), "+f"(c[2]), "+f"(c[3])
        : "r"(a[0]), "r"(a[1]), "r"(a[2]), "r"(a[3]), "r"(b0), "r"(b1));
}

__global__ void __launch_bounds__(256, 2) xproj_tc_kernel(
    const float* __restrict__ inp, const float* __restrict__ W,
    const float* __restrict__ bb, const float* __restrict__ dp)
{
    extern __shared__ char smx[];
    const uint32_t sb = smem_u32(smx);
    const int b   = blockIdx.x;
    const int ny  = blockIdx.y;            // n-half: cols [ny*80, ny*80+80)
    const int mt  = blockIdx.z;            // m-half: tiles {2mt, 2mt+1}
    const int n0g = ny * TNH;
    const int tid = threadIdx.x;
    const int wid = tid >> 5;
    const int lid = tid & 31;

    float* bias_s = reinterpret_cast<float*>(smx + SX_BIAS);
    for (int n = tid; n < XP; n += 256)
        bias_s[n] = (n < NC) ? bb[n] : 0.f;

    // Build B half = Weff^T rows [n0g, n0g+80) (hi/lo bf16), stride LDAB.
    {
        __nv_bfloat162* BH = reinterpret_cast<__nv_bfloat162*>(smx + SX_BH);
        __nv_bfloat162* BL = reinterpret_cast<__nv_bfloat162*>(smx + SX_BL);
        for (int i = tid; i < TNH * (TK / 2); i += 256) {
            int kp = i / TNH, n = i - kp * TNH;
            int ng = n0g + n;
            int k0 = 2 * kp;
            float w0 = 0.f, w1 = 0.f;
            if (ng < NC) {
                int g = ng / NU;
                w0 = W[k0 * NC + ng]       * dp[g * (B_ * F_) + b * F_ + k0];
                w1 = W[(k0 + 1) * NC + ng] * dp[g * (B_ * F_) + b * F_ + k0 + 1];
            }
            __nv_bfloat16 h0 = __float2bfloat16(w0);
            __nv_bfloat16 h1 = __float2bfloat16(w1);
            __nv_bfloat16 l0 = __float2bfloat16(w0 - __bfloat162float(h0));
            __nv_bfloat16 l1 = __float2bfloat16(w1 - __bfloat162float(h1));
            uint32_t off = (uint32_t)(n * (LDAB / 2) + kp);
            BH[off] = __nv_bfloat162(h0, h1);
            BL[off] = __nv_bfloat162(l0, l1);
        }
    }

    const int m0 = wid * 16;
    const uint32_t a_lane = (uint32_t)(((m0 + (lid & 15)) * LDAB + ((lid >> 4) << 3)) * 2);
    const uint32_t b_lane = (uint32_t)(((((lid & 7) + ((lid >> 4) << 3)) * LDAB) +
                                        (((lid >> 3) & 1) << 3)) * 2);
    const uint32_t ah_base = sb + SX_AH + a_lane;
    const uint32_t al_base = sb + SX_AL + a_lane;
    const uint32_t bh_base = sb + SX_BH + b_lane;
    const uint32_t bl_base = sb + SX_BL + b_lane;

    for (int tile = mt * 2; tile < mt * 2 + 2; ++tile) {
        const int t0 = tile * TM;
        __syncthreads();   // prev tile's ldmatrix done (covers B build on tile 0)

        // Stage A tile (hi/lo bf16), rows m, cols k, stride LDAB.
        {
            __nv_bfloat162* AH = reinterpret_cast<__nv_bfloat162*>(smx + SX_AH);
            __nv_bfloat162* AL = reinterpret_cast<__nv_bfloat162*>(smx + SX_AL);
            const float2* src = reinterpret_cast<const float2*>(
                inp + ((size_t)b * T_ + t0) * F_);
            for (int i = tid; i < TM * (TK / 2); i += 256) {
                int m = i >> 6, kp = i & 63;
                float2 v = src[i];
                __nv_bfloat16 h0 = __float2bfloat16(v.x);
                __nv_bfloat16 h1 = __float2bfloat16(v.y);
                __nv_bfloat16 l0 = __float2bfloat16(v.x - __bfloat162float(h0));
                __nv_bfloat16 l1 = __float2bfloat16(v.y - __bfloat162float(h1));
                uint32_t off = (uint32_t)(m * (LDAB / 2) + kp);
                AH[off] = __nv_bfloat162(h0, h1);
                AL[off] = __nv_bfloat162(l0, l1);
            }
        }
        __syncthreads();

        float c[10][4];
        #pragma unroll
        for (int nb = 0; nb < 10; ++nb)
            #pragma unroll
            for (int q = 0; q < 4; ++q) c[nb][q] = 0.f;

        #pragma unroll
        for (int ks = 0; ks < 8; ++ks) {
            const uint32_t kb = (uint32_t)(ks * 32);
            uint32_t ah[4], al[4];
            ldmx4(ah, ah_base + kb);
            ldmx4(al, al_base + kb);
            #pragma unroll
            for (int p = 0; p < 5; ++p) {
                const uint32_t nboff = (uint32_t)(p * 16 * LDAB * 2) + kb;
                uint32_t bh[4], bl[4];
                ldmx4(bh, bh_base + nboff);
                ldmx4(bl, bl_base + nboff);
                mma16816(c[2 * p],     ah, bh[0], bh[1]);
                mma16816(c[2 * p],     ah, bl[0], bl[1]);
                mma16816(c[2 * p],     al, bh[0], bh[1]);
                mma16816(c[2 * p + 1], ah, bh[2], bh[3]);
                mma16816(c[2 * p + 1], ah, bl[2], bl[3]);
                mma16816(c[2 * p + 1], al, bh[2], bh[3]);
            }
        }

        const int rrow = m0 + (lid >> 2);
        const int ccol = (lid & 3) * 2;
        float* o0 = g_X + ((size_t)b * T_ + t0 + rrow) * XP;
        float* o1 = o0 + 8 * XP;
        #pragma unroll
        for (int nb = 0; nb < 10; ++nb) {
            int col = n0g + nb * 8 + ccol;
            float2 bz = *reinterpret_cast<const float2*>(bias_s + col);
            float2 v0 = make_float2(c[nb][0] + bz.x, c[nb][1] + bz.y);
            float2 v1 = make_float2(c[nb][2] + bz.x, c[nb][3] + bz.y);
            *reinterpret_cast<float2*>(o0 + col) = v0;
            *reinterpret_cast<float2*>(o1 + col) = v1;
        }
    }
}

// ---------------- Kernel 2: recurrent scan (1 row/CTA, occ 4) ---------------
// 512 CTAs x 128 threads: u = tid&63, s = tid>>6 (2-way split-K, JSEG=25).
// Decoupled finalizers: thread (u,s) finalizes unit u iff u/25 == s, so each
// hm region is written+read within one half -> the post-update barrier is a
// per-half named bar.sync(64). Cross-half 'part' exchange is double-buffered
// by step parity (full BAR0 per step bounds skew). CH=16.
#define SJSEG 25
#define SCH   16                       // steps per chunk
#define SXQ   38                       // float4 per step (152 floats)
#define SXROWF4 (SCH * SXQ + 2)        // +32B pad
#define SCHUNK_F4 (SCH * SXQ)          // 608

__global__ void __launch_bounds__(128, 4) scan_kernel(
    const float* __restrict__ U, const float* __restrict__ bb,
    const float* __restrict__ Wd, const float* __restrict__ bd,
    const float* __restrict__ rdp, float* __restrict__ out)
{
    __shared__ __align__(16) float hm[3][64];   // [gate][slot]; slot=u+(u>=25)*7
    __shared__ float4 part[2][2][64];           // [parity][src half][u]
    __shared__ float4 Xs[2 * SXROWF4];          // double-buffered X chunks
    __shared__ float  head[64];

    const int tid = threadIdx.x;
    const int u   = tid & 63;               // unit (active if < 50)
    const int s   = tid >> 6;               // j-half
    const int b   = blockIdx.x;             // one batch row
    const bool active = (u < NU);
    const bool fin    = active && ((u / SJSEG) == s);   // finalizer for unit u
    const bool expt   = active && ((u / SJSEG) != s);   // exports partial
    const int rbase = s * 32;                // hm region base (128B aligned)
    const int slot  = u + ((u >= SJSEG) ? 7 : 0);

    for (int idx = tid; idx < 3 * 64; idx += 128)
        (&hm[0][0])[idx] = 0.f;

    // U slice in scalar registers: j = s*25 + jj
    float Uz[SJSEG], Ur[SJSEG], Uh[SJSEG];
    #pragma unroll
    for (int jj = 0; jj < SJSEG; ++jj) {
        int j = s * SJSEG + jj;
        float vz = 0.f, vr = 0.f, vh = 0.f;
        if (active) {
            vz = U[j * NC + u];
            vr = U[j * NC + NU + u];
            vh = U[j * NC + 2 * NU + u];
        }
        Uz[jj] = vz; Ur[jj] = vr; Uh[jj] = vh;
    }

    float br0 = 0.f, br1 = 0.f, br2 = 0.f, wdu = 0.f;
    float rdp0 = 0.f, rdp1 = 0.f, rdp2 = 0.f, h = 0.f;
    if (fin) {
        br0 = bb[NC + u]; br1 = bb[NC + NU + u]; br2 = bb[NC + 2 * NU + u];
        wdu = Wd[u];
        rdp0 = rdp[0 * (B_ * NU) + b * NU + u];
        rdp1 = rdp[1 * (B_ * NU) + b * NU + u];
        rdp2 = rdp[2 * (B_ * NU) + b * NU + u];
    }

    // ---- cp.async chunk loader (all 128 threads) ----
    const uint32_t xs_base = smem_u32(&Xs[0]);
    auto issue_chunk = [&](int c, int buf) {
        #pragma unroll
        for (int it = 0; it < 5; ++it) {
            int lin = it * 128 + tid;
            if (lin < SCHUNK_F4) {
                int tt = lin / SXQ;
                int q  = lin - tt * SXQ;
                const float* g = g_X + ((size_t)b * T_ + c * SCH + tt) * XP + q * 4;
                uint32_t dst = xs_base +
                    (uint32_t)(buf * SXROWF4 + tt * SXQ + q) * 16u;
                asm volatile("cp.async.cg.shared.global [%0], [%1], 16;"
                             :: "r"(dst), "l"(g) : "memory");
            }
        }
        asm volatile("cp.async.commit_group;" ::: "memory");
    };

    issue_chunk(0, 0);
    issue_chunk(1, 1);
    asm volatile("cp.async.wait_group 1;" ::: "memory");   // chunk 0 ready
    __syncthreads();

    const float* XsF = reinterpret_cast<const float*>(Xs);
    const int NCHUNK = T_ / SCH;   // 32
    for (int c = 0; c < NCHUNK; ++c) {
        const int buf = c & 1;
        const float* Xrow = XsF + (size_t)buf * (SXROWF4 * 4);

        #pragma unroll 2
        for (int tt = 0; tt < SCH; ++tt) {
            const int p = tt & 1;          // part parity (SCH even -> consistent)

            // phase A: split-K partials, scalar FFMA, broadcast LDS.128
            float az = 0.f, ar = 0.f, ah = 0.f;
            const float4* hz4 = reinterpret_cast<const float4*>(&hm[0][rbase]);
            const float4* hr4 = reinterpret_cast<const float4*>(&hm[1][rbase]);
            const float4* hh4 = reinterpret_cast<const float4*>(&hm[2][rbase]);
            #pragma unroll
            for (int i = 0; i < 6; ++i) {
                float4 vz = hz4[i], vr = hr4[i], vh = hh4[i];
                az = fmaf(vz.x, Uz[4*i+0], az); ar = fmaf(vr.x, Ur[4*i+0], ar);
                ah = fmaf(vh.x, Uh[4*i+0], ah);
                az = fmaf(vz.y, Uz[4*i+1], az); ar = fmaf(vr.y, Ur[4*i+1], ar);
                ah = fmaf(vh.y, Uh[4*i+1], ah);
                az = fmaf(vz.z, Uz[4*i+2], az); ar = fmaf(vr.z, Ur[4*i+2], ar);
                ah = fmaf(vh.z, Uh[4*i+2], ah);
                az = fmaf(vz.w, Uz[4*i+3], az); ar = fmaf(vr.w, Ur[4*i+3], ar);
                ah = fmaf(vh.w, Uh[4*i+3], ah);
            }
            az = fmaf(hm[0][rbase + 24], Uz[24], az);
            ar = fmaf(hm[1][rbase + 24], Ur[24], ar);
            ah = fmaf(hm[2][rbase + 24], Uh[24], ah);

            if (expt) part[p][s][u] = make_float4(az, ar, ah, 0.f);
            __syncthreads();               // BAR0: cross-half exchange

            // phase B: finalizers (u/25 == s) combine, update h, write own hm
            if (fin) {
                float4 q = part[p][1 - s][u];
                float sz = az + q.x, sr = ar + q.y, sh = ah + q.z;
                const float* Xp = Xrow + tt * (SXQ * 4);
                float xz = Xp[u], xr = Xp[NU + u], xh = Xp[2 * NU + u];
                float z  = sigm(xz + sz + br0);
                float r  = sigm(xr + sr + br1);
                float th = tanh_fast(xh + r * (sh + br2));
                h = z * h + (1.f - z) * th;
                hm[0][slot] = h * rdp0;
                hm[1][slot] = h * rdp1;
                hm[2][slot] = h * rdp2;
            }
            // per-half named barrier: hm region is produced+consumed in-half
            asm volatile("bar.sync %0, 64;" :: "r"(s + 1) : "memory");
        }

        // chunk boundary: refill consumed buffer with chunk c+2
        if (c + 2 < NCHUNK) {
            issue_chunk(c + 2, buf);
            asm volatile("cp.async.wait_group 1;" ::: "memory");  // c+1 ready
        } else {
            asm volatile("cp.async.wait_group 0;" ::: "memory");  // drain all
        }
        __syncthreads();
    }

    // dense head: out[b] = h . Wd + bd
    if (fin) head[u] = h * wdu;
    __syncthreads();
    if (tid == 0) {
        float sum = bd[0];
        for (int uu = 0; uu < NU; ++uu) sum += head[uu];
        out[b] = sum;
    }
}

// ---------------- launch ----------------
extern "C" void kernel_launch(void* const* d_in, const int* in_sizes, int n_in,
                              void* d_out, int out_size)
{
    const float* inp = (const float*)d_in[0];
    const float* W   = (const float*)d_in[1];
    const float* U   = (const float*)d_in[2];
    const float* bb  = (const float*)d_in[3];
    const float* Wd  = (const float*)d_in[4];
    const float* bd  = (const float*)d_in[5];
    const float* dp  = (const float*)d_in[6];
    const float* rdp = (const float*)d_in[7];
    float* out = (float*)d_out;

    cudaFuncSetAttribute(xproj_tc_kernel, cudaFuncAttributeMaxDynamicSharedMemorySize, SX_TOT);
    dim3 grid(B_, 2, 2);
    xproj_tc_kernel<<<grid, 256, SX_TOT>>>(inp, W, bb, dp);
    scan_kernel<<<B_, 128>>>(U, bb, Wd, bd, rdp, out);
}

// round 13
// speedup vs baseline: 1.0089x; 1.0089x over previous
#include <cuda_runtime.h>
#include <cuda_bf16.h>
#include <cstdint>

#define B_  512
#define T_  512
#define F_  128
#define NU  50
#define NC  150   // 3*NU
#define XP  160   // padded X row (floats)

// Scratch for projected inputs X[b][t][160].
__device__ float g_X[(size_t)B_ * T_ * XP];

typedef unsigned long long ull;

__device__ __forceinline__ float sigm(float x) {
    return __fdividef(1.f, 1.f + __expf(-x));
}
__device__ __forceinline__ float tanh_fast(float x) {
    return __fdividef(2.f, 1.f + __expf(-2.f * x)) - 1.f;
}
__device__ __forceinline__ uint32_t smem_u32(const void* p) {
    uint32_t a;
    asm("{ .reg .u64 t; cvta.to.shared.u64 t, %1; cvt.u32.u64 %0, t; }"
        : "=r"(a) : "l"(p));
    return a;
}

// ================= Kernel 1: xproj via HMMA, N split over 2 CTAs (R11) ======
#define TM   128
#define TNH  80                          // N per CTA
#define TK   128
#define LDAB 136                         // bf16 stride (272B, ldmatrix-friendly)

#define SX_BIAS 0                                   // 160 floats (global cols)
#define SX_BH   1024                                // 80*136*2 = 21760
#define SX_BL   (SX_BH + TNH * LDAB * 2)
#define SX_AH   (SX_BL + TNH * LDAB * 2)
#define SX_AL   (SX_AH + TM * LDAB * 2)
#define SX_TOT  (SX_AL + TM * LDAB * 2)             // 114176 (~111.5KB)

__device__ __forceinline__ void ldmx4(uint32_t* r, uint32_t addr) {
    asm volatile("ldmatrix.sync.aligned.m8n8.x4.shared.b16 {%0,%1,%2,%3}, [%4];"
                 : "=r"(r[0]), "=r"(r[1]), "=r"(r[2]), "=r"(r[3]) : "r"(addr));
}
__device__ __forceinline__ void mma16816(float* c, const uint32_t* a,
                                         uint32_t b0, uint32_t b1) {
    asm volatile(
        "mma.sync.aligned.m16n8k16.row.col.f32.bf16.bf16.f32 "
        "{%0,%1,%2,%3}, {%4,%5,%6,%7}, {%8,%9}, {%0,%1,%2,%3};"
        : "+f"(c[0]), "+f"(c[1]), "+f"(c[2]), "+f"(c[3])
        : "r"(a[0]), "r"(a[1]), "r"(a[2]), "r"(a[3]), "r"(b0), "r"(b1));
}

__global__ void __launch_bounds__(256, 2) xproj_tc_kernel(
    const float* __restrict__ inp, const float* __restrict__ W,
    const float* __restrict__ bb, const float* __restrict__ dp)
{
    extern __shared__ char smx[];
    const uint32_t sb = smem_u32(smx);
    const int b   = blockIdx.x;
    const int ny  = blockIdx.y;            // n-half: cols [ny*80, ny*80+80)
    const int n0g = ny * TNH;
    const int tid = threadIdx.x;
    const int wid = tid >> 5;
    const int lid = tid & 31;

    float* bias_s = reinterpret_cast<float*>(smx + SX_BIAS);
    for (int n = tid; n < XP; n += 256)
        bias_s[n] = (n < NC) ? bb[n] : 0.f;

    // Build B half = Weff^T rows [n0g, n0g+80) (hi/lo bf16), stride LDAB.
    {
        __nv_bfloat162* BH = reinterpret_cast<__nv_bfloat162*>(smx + SX_BH);
        __nv_bfloat162* BL = reinterpret_cast<__nv_bfloat162*>(smx + SX_BL);
        for (int i = tid; i < TNH * (TK / 2); i += 256) {
            int kp = i / TNH, n = i - kp * TNH;
            int ng = n0g + n;
            int k0 = 2 * kp;
            float w0 = 0.f, w1 = 0.f;
            if (ng < NC) {
                int g = ng / NU;
                w0 = W[k0 * NC + ng]       * dp[g * (B_ * F_) + b * F_ + k0];
                w1 = W[(k0 + 1) * NC + ng] * dp[g * (B_ * F_) + b * F_ + k0 + 1];
            }
            __nv_bfloat16 h0 = __float2bfloat16(w0);
            __nv_bfloat16 h1 = __float2bfloat16(w1);
            __nv_bfloat16 l0 = __float2bfloat16(w0 - __bfloat162float(h0));
            __nv_bfloat16 l1 = __float2bfloat16(w1 - __bfloat162float(h1));
            uint32_t off = (uint32_t)(n * (LDAB / 2) + kp);
            BH[off] = __nv_bfloat162(h0, h1);
            BL[off] = __nv_bfloat162(l0, l1);
        }
    }

    const int m0 = wid * 16;
    const uint32_t a_lane = (uint32_t)(((m0 + (lid & 15)) * LDAB + ((lid >> 4) << 3)) * 2);
    const uint32_t b_lane = (uint32_t)(((((lid & 7) + ((lid >> 4) << 3)) * LDAB) +
                                        (((lid >> 3) & 1) << 3)) * 2);
    const uint32_t ah_base = sb + SX_AH + a_lane;
    const uint32_t al_base = sb + SX_AL + a_lane;
    const uint32_t bh_base = sb + SX_BH + b_lane;
    const uint32_t bl_base = sb + SX_BL + b_lane;

    for (int tile = 0; tile < T_ / TM; ++tile) {
        const int t0 = tile * TM;
        __syncthreads();   // prev tile's ldmatrix done (covers B build on tile 0)

        // Stage A tile (hi/lo bf16), rows m, cols k, stride LDAB.
        {
            __nv_bfloat162* AH = reinterpret_cast<__nv_bfloat162*>(smx + SX_AH);
            __nv_bfloat162* AL = reinterpret_cast<__nv_bfloat162*>(smx + SX_AL);
            const float2* src = reinterpret_cast<const float2*>(
                inp + ((size_t)b * T_ + t0) * F_);
            for (int i = tid; i < TM * (TK / 2); i += 256) {
                int m = i >> 6, kp = i & 63;
                float2 v = src[i];
                __nv_bfloat16 h0 = __float2bfloat16(v.x);
                __nv_bfloat16 h1 = __float2bfloat16(v.y);
                __nv_bfloat16 l0 = __float2bfloat16(v.x - __bfloat162float(h0));
                __nv_bfloat16 l1 = __float2bfloat16(v.y - __bfloat162float(h1));
                uint32_t off = (uint32_t)(m * (LDAB / 2) + kp);
                AH[off] = __nv_bfloat162(h0, h1);
                AL[off] = __nv_bfloat162(l0, l1);
            }
        }
        __syncthreads();

        float c[10][4];
        #pragma unroll
        for (int nb = 0; nb < 10; ++nb)
            #pragma unroll
            for (int q = 0; q < 4; ++q) c[nb][q] = 0.f;

        #pragma unroll
        for (int ks = 0; ks < 8; ++ks) {
            const uint32_t kb = (uint32_t)(ks * 32);
            uint32_t ah[4], al[4];
            ldmx4(ah, ah_base + kb);
            ldmx4(al, al_base + kb);
            #pragma unroll
            for (int p = 0; p < 5; ++p) {
                const uint32_t nboff = (uint32_t)(p * 16 * LDAB * 2) + kb;
                uint32_t bh[4], bl[4];
                ldmx4(bh, bh_base + nboff);
                ldmx4(bl, bl_base + nboff);
                mma16816(c[2 * p],     ah, bh[0], bh[1]);
                mma16816(c[2 * p],     ah, bl[0], bl[1]);
                mma16816(c[2 * p],     al, bh[0], bh[1]);
                mma16816(c[2 * p + 1], ah, bh[2], bh[3]);
                mma16816(c[2 * p + 1], ah, bl[2], bl[3]);
                mma16816(c[2 * p + 1], al, bh[2], bh[3]);
            }
        }

        const int rrow = m0 + (lid >> 2);
        const int ccol = (lid & 3) * 2;
        float* o0 = g_X + ((size_t)b * T_ + t0 + rrow) * XP;
        float* o1 = o0 + 8 * XP;
        #pragma unroll
        for (int nb = 0; nb < 10; ++nb) {
            int col = n0g + nb * 8 + ccol;
            float2 bz = *reinterpret_cast<const float2*>(bias_s + col);
            float2 v0 = make_float2(c[nb][0] + bz.x, c[nb][1] + bz.y);
            float2 v1 = make_float2(c[nb][2] + bz.x, c[nb][3] + bz.y);
            *reinterpret_cast<float2*>(o0 + col) = v0;
            *reinterpret_cast<float2*>(o1 + col) = v1;
        }
    }
}

// ---------------- Kernel 2: recurrent scan (R11 + chain cuts) ---------------
// 512 CTAs x 1 batch row, 128 threads (4 warps): u = tid&63, s = tid>>6
// (2-way split-K, JSEG=25). U in 75 scalar regs; scalar FFMA gates.
// R13 changes vs R11: (1) each gate accumulator split into 2 sub-chains
// (25-deep -> ~13-deep), (2) X loads hoisted above phase A.
#define SJSEG 25
#define SCH   8                        // steps per chunk
#define SXQ   38                       // float4 per step (152 floats)
#define SXROWF4 (SCH * SXQ + 2)        // 306 (+32B pad)
#define SCHUNK_F4 (SCH * SXQ)          // 304

__global__ void __launch_bounds__(128, 4) scan_kernel(
    const float* __restrict__ U, const float* __restrict__ bb,
    const float* __restrict__ Wd, const float* __restrict__ bd,
    const float* __restrict__ rdp, float* __restrict__ out)
{
    __shared__ __align__(16) float hm[3][64];   // [gate][slot]; slot=j+(j>=25)*7
    __shared__ float4 part1[64];                // s=1 partials {z,r,h,_}
    __shared__ float4 Xs[2 * SXROWF4];          // double-buffered X chunks
    __shared__ float  head[64];

    const int tid = threadIdx.x;
    const int u   = tid & 63;               // unit (active if < 50)
    const int s   = tid >> 6;               // j-half
    const int b   = blockIdx.x;             // one batch row
    const bool active = (u < NU);
    const bool fin    = (s == 0) && active; // finalizer for unit u
    const int rbase = s * 32;               // hm region base (128B aligned)
    const int slot  = u + ((u >= SJSEG) ? 7 : 0);

    for (int idx = tid; idx < 3 * 64; idx += 128)
        (&hm[0][0])[idx] = 0.f;

    // U slice in scalar registers: j = s*25 + jj
    float Uz[SJSEG], Ur[SJSEG], Uh[SJSEG];
    #pragma unroll
    for (int jj = 0; jj < SJSEG; ++jj) {
        int j = s * SJSEG + jj;
        float vz = 0.f, vr = 0.f, vh = 0.f;
        if (active) {
            vz = U[j * NC + u];
            vr = U[j * NC + NU + u];
            vh = U[j * NC + 2 * NU + u];
        }
        Uz[jj] = vz; Ur[jj] = vr; Uh[jj] = vh;
    }

    float br0 = 0.f, br1 = 0.f, br2 = 0.f, wdu = 0.f;
    float rdp0 = 0.f, rdp1 = 0.f, rdp2 = 0.f, h = 0.f;
    if (fin) {
        br0 = bb[NC + u]; br1 = bb[NC + NU + u]; br2 = bb[NC + 2 * NU + u];
        wdu = Wd[u];
        rdp0 = rdp[0 * (B_ * NU) + b * NU + u];
        rdp1 = rdp[1 * (B_ * NU) + b * NU + u];
        rdp2 = rdp[2 * (B_ * NU) + b * NU + u];
    }

    // ---- cp.async chunk loader (all 128 threads) ----
    const uint32_t xs_base = smem_u32(&Xs[0]);
    auto issue_chunk = [&](int c, int buf) {
        #pragma unroll
        for (int it = 0; it < 3; ++it) {
            int lin = it * 128 + tid;
            if (lin < SCHUNK_F4) {
                int tt = lin / SXQ;
                int q  = lin - tt * SXQ;
                const float* g = g_X + ((size_t)b * T_ + c * SCH + tt) * XP + q * 4;
                uint32_t dst = xs_base +
                    (uint32_t)(buf * SXROWF4 + tt * SXQ + q) * 16u;
                asm volatile("cp.async.cg.shared.global [%0], [%1], 16;"
                             :: "r"(dst), "l"(g) : "memory");
            }
        }
        asm volatile("cp.async.commit_group;" ::: "memory");
    };

    issue_chunk(0, 0);
    issue_chunk(1, 1);
    asm volatile("cp.async.wait_group 1;" ::: "memory");   // chunk 0 ready
    __syncthreads();

    const float* XsF = reinterpret_cast<const float*>(Xs);
    const int NCHUNK = T_ / SCH;   // 64
    for (int c = 0; c < NCHUNK; ++c) {
        const int buf = c & 1;
        const float* Xrow = XsF + (size_t)buf * (SXROWF4 * 4);

        #pragma unroll 2
        for (int tt = 0; tt < SCH; ++tt) {
            // X prefetch (only fin threads need it; issued BEFORE phase A so
            // its LDS latency hides under the FFMA block)
            float xz = 0.f, xr = 0.f, xh = 0.f;
            if (fin) {
                const float* Xp = Xrow + tt * (SXQ * 4);
                xz = Xp[u]; xr = Xp[NU + u]; xh = Xp[2 * NU + u];
            }

            // phase A: split-K partials, 2 sub-chains per gate
            float az0 = 0.f, az1 = 0.f, ar0 = 0.f, ar1 = 0.f, ah0 = 0.f, ah1 = 0.f;
            const float4* hz4 = reinterpret_cast<const float4*>(&hm[0][rbase]);
            const float4* hr4 = reinterpret_cast<const float4*>(&hm[1][rbase]);
            const float4* hh4 = reinterpret_cast<const float4*>(&hm[2][rbase]);
            #pragma unroll
            for (int i = 0; i < 3; ++i) {
                float4 vz = hz4[i], vr = hr4[i], vh = hh4[i];
                az0 = fmaf(vz.x, Uz[4*i+0], az0); ar0 = fmaf(vr.x, Ur[4*i+0], ar0);
                ah0 = fmaf(vh.x, Uh[4*i+0], ah0);
                az0 = fmaf(vz.y, Uz[4*i+1], az0); ar0 = fmaf(vr.y, Ur[4*i+1], ar0);
                ah0 = fmaf(vh.y, Uh[4*i+1], ah0);
                az0 = fmaf(vz.z, Uz[4*i+2], az0); ar0 = fmaf(vr.z, Ur[4*i+2], ar0);
                ah0 = fmaf(vh.z, Uh[4*i+2], ah0);
                az0 = fmaf(vz.w, Uz[4*i+3], az0); ar0 = fmaf(vr.w, Ur[4*i+3], ar0);
                ah0 = fmaf(vh.w, Uh[4*i+3], ah0);
            }
            #pragma unroll
            for (int i = 3; i < 6; ++i) {
                float4 vz = hz4[i], vr = hr4[i], vh = hh4[i];
                az1 = fmaf(vz.x, Uz[4*i+0], az1); ar1 = fmaf(vr.x, Ur[4*i+0], ar1);
                ah1 = fmaf(vh.x, Uh[4*i+0], ah1);
                az1 = fmaf(vz.y, Uz[4*i+1], az1); ar1 = fmaf(vr.y, Ur[4*i+1], ar1);
                ah1 = fmaf(vh.y, Uh[4*i+1], ah1);
                az1 = fmaf(vz.z, Uz[4*i+2], az1); ar1 = fmaf(vr.z, Ur[4*i+2], ar1);
                ah1 = fmaf(vh.z, Uh[4*i+2], ah1);
                az1 = fmaf(vz.w, Uz[4*i+3], az1); ar1 = fmaf(vr.w, Ur[4*i+3], ar1);
                ah1 = fmaf(vh.w, Uh[4*i+3], ah1);
            }
            az1 = fmaf(hm[0][rbase + 24], Uz[24], az1);
            ar1 = fmaf(hm[1][rbase + 24], Ur[24], ar1);
            ah1 = fmaf(hm[2][rbase + 24], Uh[24], ah1);
            float az = az0 + az1, ar = ar0 + ar1, ah = ah0 + ah1;

            if (s) part1[u] = make_float4(az, ar, ah, 0.f);
            __syncthreads();

            // phase B: finalizers combine 2 partials, update h, broadcast
            if (fin) {
                float4 p = part1[u];
                float sz = az + p.x, sr = ar + p.y, sh = ah + p.z;
                float z  = sigm(xz + sz + br0);
                float r  = sigm(xr + sr + br1);
                float th = tanh_fast(xh + r * (sh + br2));
                h = z * h + (1.f - z) * th;
                hm[0][slot] = h * rdp0;
                hm[1][slot] = h * rdp1;
                hm[2][slot] = h * rdp2;
            }
            __syncthreads();
        }

        // chunk boundary: refill consumed buffer with chunk c+2
        if (c + 2 < NCHUNK) {
            issue_chunk(c + 2, buf);
            asm volatile("cp.async.wait_group 1;" ::: "memory");  // c+1 ready
        } else {
            asm volatile("cp.async.wait_group 0;" ::: "memory");  // drain all
        }
        __syncthreads();
    }

    // dense head: out[b] = h . Wd + bd
    if (fin) head[u] = h * wdu;
    __syncthreads();
    if (tid == 0) {
        float sum = bd[0];
        for (int uu = 0; uu < NU; ++uu) sum += head[uu];
        out[b] = sum;
    }
}

// ---------------- launch ----------------
extern "C" void kernel_launch(void* const* d_in, const int* in_sizes, int n_in,
                              void* d_out, int out_size)
{
    const float* inp = (const float*)d_in[0];
    const float* W   = (const float*)d_in[1];
    const float* U   = (const float*)d_in[2];
    const float* bb  = (const float*)d_in[3];
    const float* Wd  = (const float*)d_in[4];
    const float* bd  = (const float*)d_in[5];
    const float* dp  = (const float*)d_in[6];
    const float* rdp = (const float*)d_in[7];
    float* out = (float*)d_out;

    cudaFuncSetAttribute(xproj_tc_kernel, cudaFuncAttributeMaxDynamicSharedMemorySize, SX_TOT);
    dim3 grid(B_, 2);
    xproj_tc_kernel<<<grid, 256, SX_TOT>>>(inp, W, bb, dp);
    scan_kernel<<<B_, 128>>>(U, bb, Wd, bd, rdp, out);
}

// round 14
// speedup vs baseline: 1.0301x; 1.0210x over previous
#include <cuda_runtime.h>
#include <cuda_bf16.h>
#include <cstdint>

#define B_  512
#define T_  512
#define F_  128
#define NU  50
#define NC  150   // 3*NU
#define XP  160   // padded X row (floats)

// Scratch for projected inputs X[b][t][160].
__device__ float g_X[(size_t)B_ * T_ * XP];

typedef unsigned long long ull;

__device__ __forceinline__ float sigm(float x) {
    return __fdividef(1.f, 1.f + __expf(-x));
}
__device__ __forceinline__ float tanh_fast(float x) {
    return __fdividef(2.f, 1.f + __expf(-2.f * x)) - 1.f;
}
__device__ __forceinline__ uint32_t smem_u32(const void* p) {
    uint32_t a;
    asm("{ .reg .u64 t; cvta.to.shared.u64 t, %1; cvt.u32.u64 %0, t; }"
        : "=r"(a) : "l"(p));
    return a;
}

// ================= Kernel 1: xproj via HMMA, N split over 2 CTAs (R11) ======
#define TM   128
#define TNH  80                          // N per CTA
#define TK   128
#define LDAB 136                         // bf16 stride (272B, ldmatrix-friendly)

#define SX_BIAS 0                                   // 160 floats (global cols)
#define SX_BH   1024                                // 80*136*2 = 21760
#define SX_BL   (SX_BH + TNH * LDAB * 2)
#define SX_AH   (SX_BL + TNH * LDAB * 2)
#define SX_AL   (SX_AH + TM * LDAB * 2)
#define SX_TOT  (SX_AL + TM * LDAB * 2)             // 114176 (~111.5KB)

__device__ __forceinline__ void ldmx4(uint32_t* r, uint32_t addr) {
    asm volatile("ldmatrix.sync.aligned.m8n8.x4.shared.b16 {%0,%1,%2,%3}, [%4];"
                 : "=r"(r[0]), "=r"(r[1]), "=r"(r[2]), "=r"(r[3]) : "r"(addr));
}
__device__ __forceinline__ void mma16816(float* c, const uint32_t* a,
                                         uint32_t b0, uint32_t b1) {
    asm volatile(
        "mma.sync.aligned.m16n8k16.row.col.f32.bf16.bf16.f32 "
        "{%0,%1,%2,%3}, {%4,%5,%6,%7}, {%8,%9}, {%0,%1,%2,%3};"
        : "+f"(c[0]), "+f"(c[1]), "+f"(c[2]), "+f"(c[3])
        : "r"(a[0]), "r"(a[1]), "r"(a[2]), "r"(a[3]), "r"(b0), "r"(b1));
}

__global__ void __launch_bounds__(256, 2) xproj_tc_kernel(
    const float* __restrict__ inp, const float* __restrict__ W,
    const float* __restrict__ bb, const float* __restrict__ dp)
{
    extern __shared__ char smx[];
    const uint32_t sb = smem_u32(smx);
    const int b   = blockIdx.x;
    const int ny  = blockIdx.y;            // n-half: cols [ny*80, ny*80+80)
    const int n0g = ny * TNH;
    const int tid = threadIdx.x;
    const int wid = tid >> 5;
    const int lid = tid & 31;

    float* bias_s = reinterpret_cast<float*>(smx + SX_BIAS);
    for (int n = tid; n < XP; n += 256)
        bias_s[n] = (n < NC) ? bb[n] : 0.f;

    // Build B half = Weff^T rows [n0g, n0g+80) (hi/lo bf16), stride LDAB.
    {
        __nv_bfloat162* BH = reinterpret_cast<__nv_bfloat162*>(smx + SX_BH);
        __nv_bfloat162* BL = reinterpret_cast<__nv_bfloat162*>(smx + SX_BL);
        for (int i = tid; i < TNH * (TK / 2); i += 256) {
            int kp = i / TNH, n = i - kp * TNH;
            int ng = n0g + n;
            int k0 = 2 * kp;
            float w0 = 0.f, w1 = 0.f;
            if (ng < NC) {
                int g = ng / NU;
                w0 = W[k0 * NC + ng]       * dp[g * (B_ * F_) + b * F_ + k0];
                w1 = W[(k0 + 1) * NC + ng] * dp[g * (B_ * F_) + b * F_ + k0 + 1];
            }
            __nv_bfloat16 h0 = __float2bfloat16(w0);
            __nv_bfloat16 h1 = __float2bfloat16(w1);
            __nv_bfloat16 l0 = __float2bfloat16(w0 - __bfloat162float(h0));
            __nv_bfloat16 l1 = __float2bfloat16(w1 - __bfloat162float(h1));
            uint32_t off = (uint32_t)(n * (LDAB / 2) + kp);
            BH[off] = __nv_bfloat162(h0, h1);
            BL[off] = __nv_bfloat162(l0, l1);
        }
    }

    const int m0 = wid * 16;
    const uint32_t a_lane = (uint32_t)(((m0 + (lid & 15)) * LDAB + ((lid >> 4) << 3)) * 2);
    const uint32_t b_lane = (uint32_t)(((((lid & 7) + ((lid >> 4) << 3)) * LDAB) +
                                        (((lid >> 3) & 1) << 3)) * 2);
    const uint32_t ah_base = sb + SX_AH + a_lane;
    const uint32_t al_base = sb + SX_AL + a_lane;
    const uint32_t bh_base = sb + SX_BH + b_lane;
    const uint32_t bl_base = sb + SX_BL + b_lane;

    for (int tile = 0; tile < T_ / TM; ++tile) {
        const int t0 = tile * TM;
        __syncthreads();   // prev tile's ldmatrix done (covers B build on tile 0)

        // Stage A tile (hi/lo bf16), rows m, cols k, stride LDAB.
        {
            __nv_bfloat162* AH = reinterpret_cast<__nv_bfloat162*>(smx + SX_AH);
            __nv_bfloat162* AL = reinterpret_cast<__nv_bfloat162*>(smx + SX_AL);
            const float2* src = reinterpret_cast<const float2*>(
                inp + ((size_t)b * T_ + t0) * F_);
            for (int i = tid; i < TM * (TK / 2); i += 256) {
                int m = i >> 6, kp = i & 63;
                float2 v = src[i];
                __nv_bfloat16 h0 = __float2bfloat16(v.x);
                __nv_bfloat16 h1 = __float2bfloat16(v.y);
                __nv_bfloat16 l0 = __float2bfloat16(v.x - __bfloat162float(h0));
                __nv_bfloat16 l1 = __float2bfloat16(v.y - __bfloat162float(h1));
                uint32_t off = (uint32_t)(m * (LDAB / 2) + kp);
                AH[off] = __nv_bfloat162(h0, h1);
                AL[off] = __nv_bfloat162(l0, l1);
            }
        }
        __syncthreads();

        float c[10][4];
        #pragma unroll
        for (int nb = 0; nb < 10; ++nb)
            #pragma unroll
            for (int q = 0; q < 4; ++q) c[nb][q] = 0.f;

        #pragma unroll
        for (int ks = 0; ks < 8; ++ks) {
            const uint32_t kb = (uint32_t)(ks * 32);
            uint32_t ah[4], al[4];
            ldmx4(ah, ah_base + kb);
            ldmx4(al, al_base + kb);
            #pragma unroll
            for (int p = 0; p < 5; ++p) {
                const uint32_t nboff = (uint32_t)(p * 16 * LDAB * 2) + kb;
                uint32_t bh[4], bl[4];
                ldmx4(bh, bh_base + nboff);
                ldmx4(bl, bl_base + nboff);
                mma16816(c[2 * p],     ah, bh[0], bh[1]);
                mma16816(c[2 * p],     ah, bl[0], bl[1]);
                mma16816(c[2 * p],     al, bh[0], bh[1]);
                mma16816(c[2 * p + 1], ah, bh[2], bh[3]);
                mma16816(c[2 * p + 1], ah, bl[2], bl[3]);
                mma16816(c[2 * p + 1], al, bh[2], bh[3]);
            }
        }

        const int rrow = m0 + (lid >> 2);
        const int ccol = (lid & 3) * 2;
        float* o0 = g_X + ((size_t)b * T_ + t0 + rrow) * XP;
        float* o1 = o0 + 8 * XP;
        #pragma unroll
        for (int nb = 0; nb < 10; ++nb) {
            int col = n0g + nb * 8 + ccol;
            float2 bz = *reinterpret_cast<const float2*>(bias_s + col);
            float2 v0 = make_float2(c[nb][0] + bz.x, c[nb][1] + bz.y);
            float2 v1 = make_float2(c[nb][2] + bz.x, c[nb][3] + bz.y);
            *reinterpret_cast<float2*>(o0 + col) = v0;
            *reinterpret_cast<float2*>(o1 + col) = v1;
        }
    }
}

// ---------------- Kernel 2: recurrent scan (R11 structure, CH=16) -----------
// 512 CTAs x 1 batch row, 128 threads (4 warps): u = tid&63, s = tid>>6
// (2-way split-K, JSEG=25). U in 75 scalar regs; scalar FFMA gates.
// hm float[3][64], split regions 128B-aligned (slot = j + (j>=25)*7).
// Only s=1 writes the exchange. X via cp.async double buffer. occ 4.
// ONLY change vs R11: SCH 8 -> 16 (half the chunk-boundary overhead).
#define SJSEG 25
#define SCH   16                       // steps per chunk
#define SXQ   38                       // float4 per step (152 floats)
#define SXROWF4 (SCH * SXQ + 2)        // 610 (+32B pad)
#define SCHUNK_F4 (SCH * SXQ)          // 608

__global__ void __launch_bounds__(128, 4) scan_kernel(
    const float* __restrict__ U, const float* __restrict__ bb,
    const float* __restrict__ Wd, const float* __restrict__ bd,
    const float* __restrict__ rdp, float* __restrict__ out)
{
    __shared__ __align__(16) float hm[3][64];   // [gate][slot]; slot=j+(j>=25)*7
    __shared__ float4 part1[64];                // s=1 partials {z,r,h,_}
    __shared__ float4 Xs[2 * SXROWF4];          // double-buffered X chunks
    __shared__ float  head[64];

    const int tid = threadIdx.x;
    const int u   = tid & 63;               // unit (active if < 50)
    const int s   = tid >> 6;               // j-half
    const int b   = blockIdx.x;             // one batch row
    const bool active = (u < NU);
    const bool fin    = (s == 0) && active; // finalizer for unit u
    const int rbase = s * 32;               // hm region base (128B aligned)
    const int slot  = u + ((u >= SJSEG) ? 7 : 0);

    for (int idx = tid; idx < 3 * 64; idx += 128)
        (&hm[0][0])[idx] = 0.f;

    // U slice in scalar registers: j = s*25 + jj
    float Uz[SJSEG], Ur[SJSEG], Uh[SJSEG];
    #pragma unroll
    for (int jj = 0; jj < SJSEG; ++jj) {
        int j = s * SJSEG + jj;
        float vz = 0.f, vr = 0.f, vh = 0.f;
        if (active) {
            vz = U[j * NC + u];
            vr = U[j * NC + NU + u];
            vh = U[j * NC + 2 * NU + u];
        }
        Uz[jj] = vz; Ur[jj] = vr; Uh[jj] = vh;
    }

    float br0 = 0.f, br1 = 0.f, br2 = 0.f, wdu = 0.f;
    float rdp0 = 0.f, rdp1 = 0.f, rdp2 = 0.f, h = 0.f;
    if (fin) {
        br0 = bb[NC + u]; br1 = bb[NC + NU + u]; br2 = bb[NC + 2 * NU + u];
        wdu = Wd[u];
        rdp0 = rdp[0 * (B_ * NU) + b * NU + u];
        rdp1 = rdp[1 * (B_ * NU) + b * NU + u];
        rdp2 = rdp[2 * (B_ * NU) + b * NU + u];
    }

    // ---- cp.async chunk loader (all 128 threads) ----
    const uint32_t xs_base = smem_u32(&Xs[0]);
    auto issue_chunk = [&](int c, int buf) {
        #pragma unroll
        for (int it = 0; it < 5; ++it) {
            int lin = it * 128 + tid;
            if (lin < SCHUNK_F4) {
                int tt = lin / SXQ;
                int q  = lin - tt * SXQ;
                const float* g = g_X + ((size_t)b * T_ + c * SCH + tt) * XP + q * 4;
                uint32_t dst = xs_base +
                    (uint32_t)(buf * SXROWF4 + tt * SXQ + q) * 16u;
                asm volatile("cp.async.cg.shared.global [%0], [%1], 16;"
                             :: "r"(dst), "l"(g) : "memory");
            }
        }
        asm volatile("cp.async.commit_group;" ::: "memory");
    };

    issue_chunk(0, 0);
    issue_chunk(1, 1);
    asm volatile("cp.async.wait_group 1;" ::: "memory");   // chunk 0 ready
    __syncthreads();

    const float* XsF = reinterpret_cast<const float*>(Xs);
    const int NCHUNK = T_ / SCH;   // 32
    for (int c = 0; c < NCHUNK; ++c) {
        const int buf = c & 1;
        const float* Xrow = XsF + (size_t)buf * (SXROWF4 * 4);

        #pragma unroll 2
        for (int tt = 0; tt < SCH; ++tt) {
            // phase A: split-K partials, scalar FFMA, broadcast LDS.128
            float az = 0.f, ar = 0.f, ah = 0.f;
            const float4* hz4 = reinterpret_cast<const float4*>(&hm[0][rbase]);
            const float4* hr4 = reinterpret_cast<const float4*>(&hm[1][rbase]);
            const float4* hh4 = reinterpret_cast<const float4*>(&hm[2][rbase]);
            #pragma unroll
            for (int i = 0; i < 6; ++i) {
                float4 vz = hz4[i], vr = hr4[i], vh = hh4[i];
                az = fmaf(vz.x, Uz[4*i+0], az); ar = fmaf(vr.x, Ur[4*i+0], ar);
                ah = fmaf(vh.x, Uh[4*i+0], ah);
                az = fmaf(vz.y, Uz[4*i+1], az); ar = fmaf(vr.y, Ur[4*i+1], ar);
                ah = fmaf(vh.y, Uh[4*i+1], ah);
                az = fmaf(vz.z, Uz[4*i+2], az); ar = fmaf(vr.z, Ur[4*i+2], ar);
                ah = fmaf(vh.z, Uh[4*i+2], ah);
                az = fmaf(vz.w, Uz[4*i+3], az); ar = fmaf(vr.w, Ur[4*i+3], ar);
                ah = fmaf(vh.w, Uh[4*i+3], ah);
            }
            az = fmaf(hm[0][rbase + 24], Uz[24], az);
            ar = fmaf(hm[1][rbase + 24], Ur[24], ar);
            ah = fmaf(hm[2][rbase + 24], Uh[24], ah);

            if (s) part1[u] = make_float4(az, ar, ah, 0.f);
            __syncthreads();

            // phase B: finalizers combine 2 partials, update h, broadcast
            if (fin) {
                float4 p = part1[u];
                float sz = az + p.x, sr = ar + p.y, sh = ah + p.z;
                const float* Xp = Xrow + tt * (SXQ * 4);
                float xz = Xp[u], xr = Xp[NU + u], xh = Xp[2 * NU + u];
                float z  = sigm(xz + sz + br0);
                float r  = sigm(xr + sr + br1);
                float th = tanh_fast(xh + r * (sh + br2));
                h = z * h + (1.f - z) * th;
                hm[0][slot] = h * rdp0;
                hm[1][slot] = h * rdp1;
                hm[2][slot] = h * rdp2;
            }
            __syncthreads();
        }

        // chunk boundary: refill consumed buffer with chunk c+2
        if (c + 2 < NCHUNK) {
            issue_chunk(c + 2, buf);
            asm volatile("cp.async.wait_group 1;" ::: "memory");  // c+1 ready
        } else {
            asm volatile("cp.async.wait_group 0;" ::: "memory");  // drain all
        }
        __syncthreads();
    }

    // dense head: out[b] = h . Wd + bd
    if (fin) head[u] = h * wdu;
    __syncthreads();
    if (tid == 0) {
        float sum = bd[0];
        for (int uu = 0; uu < NU; ++uu) sum += head[uu];
        out[b] = sum;
    }
}

// ---------------- launch ----------------
extern "C" void kernel_launch(void* const* d_in, const int* in_sizes, int n_in,
                              void* d_out, int out_size)
{
    const float* inp = (const float*)d_in[0];
    const float* W   = (const float*)d_in[1];
    const float* U   = (const float*)d_in[2];
    const float* bb  = (const float*)d_in[3];
    const float* Wd  = (const float*)d_in[4];
    const float* bd  = (const float*)d_in[5];
    const float* dp  = (const float*)d_in[6];
    const float* rdp = (const float*)d_in[7];
    float* out = (float*)d_out;

    cudaFuncSetAttribute(xproj_tc_kernel, cudaFuncAttributeMaxDynamicSharedMemorySize, SX_TOT);
    dim3 grid(B_, 2);
    xproj_tc_kernel<<<grid, 256, SX_TOT>>>(inp, W, bb, dp);
    scan_kernel<<<B_, 128>>>(U, bb, Wd, bd, rdp, out);
}

// round 16
// speedup vs baseline: 1.1214x; 1.0886x over previous
#include <cuda_runtime.h>
#include <cuda_bf16.h>
#include <cstdint>

#define B_  512
#define T_  512
#define F_  128
#define NU  50
#define NC  150   // 3*NU
#define XP  160   // padded X row (floats)

// Scratch for projected inputs X[b][t][160].
__device__ float g_X[(size_t)B_ * T_ * XP];

typedef unsigned long long ull;

__device__ __forceinline__ float sigm(float x) {
    return __fdividef(1.f, 1.f + __expf(-x));
}
__device__ __forceinline__ float tanh_fast(float x) {
    return __fdividef(2.f, 1.f + __expf(-2.f * x)) - 1.f;
}
__device__ __forceinline__ uint32_t smem_u32(const void* p) {
    uint32_t a;
    asm("{ .reg .u64 t; cvta.to.shared.u64 t, %1; cvt.u32.u64 %0, t; }"
        : "=r"(a) : "l"(p));
    return a;
}

// ---- cheap bf16 hi/lo split helpers ----
__device__ __forceinline__ float trunchi(float v) {
    return __uint_as_float(__float_as_uint(v) & 0xFFFF0000u);
}
// packed bf16x2 of truncated-hi of (a, b): one PRMT (a.hi16 -> low, b.hi16 -> high)
__device__ __forceinline__ uint32_t prmt_hi(float a, float b) {
    uint32_t r;
    asm("prmt.b32 %0, %1, %2, 0x7632;"
        : "=r"(r) : "r"(__float_as_uint(a)), "r"(__float_as_uint(b)));
    return r;
}
// packed bf16x2: lo value -> low half, hi value -> high half (round-to-nearest)
__device__ __forceinline__ uint32_t bf2_rn(float lo, float hi_) {
    uint32_t r;
    asm("cvt.rn.bf16x2.f32 %0, %1, %2;" : "=r"(r) : "f"(hi_), "f"(lo));
    return r;
}

// ================= Kernel 1: xproj via HMMA, N split over 2 CTAs ============
#define TM   128
#define TNH  80                          // N per CTA
#define TK   128
#define LDAB 136                         // bf16 stride (272B, ldmatrix-friendly)

#define SX_BIAS 0                                   // 160 floats (global cols)
#define SX_BH   1024                                // 80*136*2 = 21760
#define SX_BL   (SX_BH + TNH * LDAB * 2)
#define SX_AH   (SX_BL + TNH * LDAB * 2)
#define SX_AL   (SX_AH + TM * LDAB * 2)
#define SX_TOT  (SX_AL + TM * LDAB * 2)             // 114176 (~111.5KB)

__device__ __forceinline__ void ldmx4(uint32_t* r, uint32_t addr) {
    asm volatile("ldmatrix.sync.aligned.m8n8.x4.shared.b16 {%0,%1,%2,%3}, [%4];"
                 : "=r"(r[0]), "=r"(r[1]), "=r"(r[2]), "=r"(r[3]) : "r"(addr));
}
__device__ __forceinline__ void mma16816(float* c, const uint32_t* a,
                                         uint32_t b0, uint32_t b1) {
    asm volatile(
        "mma.sync.aligned.m16n8k16.row.col.f32.bf16.bf16.f32 "
        "{%0,%1,%2,%3}, {%4,%5,%6,%7}, {%8,%9}, {%0,%1,%2,%3};"
        : "+f"(c[0]), "+f"(c[1]), "+f"(c[2]), "+f"(c[3])
        : "r"(a[0]), "r"(a[1]), "r"(a[2]), "r"(a[3]), "r"(b0), "r"(b1));
}

__global__ void __launch_bounds__(256, 2) xproj_tc_kernel(
    const float* __restrict__ inp, const float* __restrict__ W,
    const float* __restrict__ bb, const float* __restrict__ dp)
{
    extern __shared__ char smx[];
    const uint32_t sb = smem_u32(smx);
    const int b   = blockIdx.x;
    const int ny  = blockIdx.y;            // n-half: cols [ny*80, ny*80+80)
    const int n0g = ny * TNH;
    const int tid = threadIdx.x;
    const int wid = tid >> 5;
    const int lid = tid & 31;

    float* bias_s = reinterpret_cast<float*>(smx + SX_BIAS);
    for (int n = tid; n < XP; n += 256)
        bias_s[n] = (n < NC) ? bb[n] : 0.f;

    // Build B half = Weff^T rows [n0g, n0g+80) (hi/lo bf16), stride LDAB.
    {
        uint32_t* BH = reinterpret_cast<uint32_t*>(smx + SX_BH);
        uint32_t* BL = reinterpret_cast<uint32_t*>(smx + SX_BL);
        for (int i = tid; i < TNH * (TK / 2); i += 256) {
            int kp = i / TNH, n = i - kp * TNH;
            int ng = n0g + n;
            int k0 = 2 * kp;
            float w0 = 0.f, w1 = 0.f;
            if (ng < NC) {
                int g = ng / NU;
                w0 = W[k0 * NC + ng]       * dp[g * (B_ * F_) + b * F_ + k0];
                w1 = W[(k0 + 1) * NC + ng] * dp[g * (B_ * F_) + b * F_ + k0 + 1];
            }
            uint32_t off = (uint32_t)(n * (LDAB / 2) + kp);
            BH[off] = prmt_hi(w0, w1);
            BL[off] = bf2_rn(w0 - trunchi(w0), w1 - trunchi(w1));
        }
    }

    const int m0 = wid * 16;
    const uint32_t a_lane = (uint32_t)(((m0 + (lid & 15)) * LDAB + ((lid >> 4) << 3)) * 2);
    const uint32_t b_lane = (uint32_t)(((((lid & 7) + ((lid >> 4) << 3)) * LDAB) +
                                        (((lid >> 3) & 1) << 3)) * 2);
    const uint32_t ah_base = sb + SX_AH + a_lane;
    const uint32_t al_base = sb + SX_AL + a_lane;
    const uint32_t bh_base = sb + SX_BH + b_lane;
    const uint32_t bl_base = sb + SX_BL + b_lane;

    for (int tile = 0; tile < T_ / TM; ++tile) {
        const int t0 = tile * TM;
        __syncthreads();   // prev tile's ldmatrix done (covers B build on tile 0)

        // Stage A tile (hi/lo bf16): float4 loads, PRMT hi, dual-cvt lo, STS.64
        {
            uint2* AH2 = reinterpret_cast<uint2*>(smx + SX_AH);
            uint2* AL2 = reinterpret_cast<uint2*>(smx + SX_AL);
            const float4* src4 = reinterpret_cast<const float4*>(
                inp + ((size_t)b * T_ + t0) * F_);
            for (int i = tid; i < TM * (TK / 4); i += 256) {   // 4096
                int m = i >> 5, kq = i & 31;
                float4 v = src4[i];
                uint32_t h01 = prmt_hi(v.x, v.y);
                uint32_t h23 = prmt_hi(v.z, v.w);
                uint32_t l01 = bf2_rn(v.x - trunchi(v.x), v.y - trunchi(v.y));
                uint32_t l23 = bf2_rn(v.z - trunchi(v.z), v.w - trunchi(v.w));
                // bf16x2 offset = m*(LDAB/2) + 2*kq (even) -> uint2 index m*34+kq
                uint32_t o2 = (uint32_t)(m * (LDAB / 4) + kq);   // LDAB/4 = 34
                AH2[o2] = make_uint2(h01, h23);
                AL2[o2] = make_uint2(l01, l23);
            }
        }
        __syncthreads();

        float c[10][4];
        #pragma unroll
        for (int nb = 0; nb < 10; ++nb)
            #pragma unroll
            for (int q = 0; q < 4; ++q) c[nb][q] = 0.f;

        #pragma unroll
        for (int ks = 0; ks < 8; ++ks) {
            const uint32_t kb = (uint32_t)(ks * 32);
            uint32_t ah[4], al[4];
            ldmx4(ah, ah_base + kb);
            ldmx4(al, al_base + kb);
            #pragma unroll
            for (int p = 0; p < 5; ++p) {
                const uint32_t nboff = (uint32_t)(p * 16 * LDAB * 2) + kb;
                uint32_t bh[4], bl[4];
                ldmx4(bh, bh_base + nboff);
                ldmx4(bl, bl_base + nboff);
                mma16816(c[2 * p],     ah, bh[0], bh[1]);
                mma16816(c[2 * p],     ah, bl[0], bl[1]);
                mma16816(c[2 * p],     al, bh[0], bh[1]);
                mma16816(c[2 * p + 1], ah, bh[2], bh[3]);
                mma16816(c[2 * p + 1], ah, bl[2], bl[3]);
                mma16816(c[2 * p + 1], al, bh[2], bh[3]);
            }
        }

        const int rrow = m0 + (lid >> 2);
        const int ccol = (lid & 3) * 2;
        float* o0 = g_X + ((size_t)b * T_ + t0 + rrow) * XP;
        float* o1 = o0 + 8 * XP;
        #pragma unroll
        for (int nb = 0; nb < 10; ++nb) {
            int col = n0g + nb * 8 + ccol;
            float2 bz = *reinterpret_cast<const float2*>(bias_s + col);
            float2 v0 = make_float2(c[nb][0] + bz.x, c[nb][1] + bz.y);
            float2 v1 = make_float2(c[nb][2] + bz.x, c[nb][3] + bz.y);
            *reinterpret_cast<float2*>(o0 + col) = v0;
            *reinterpret_cast<float2*>(o1 + col) = v1;
        }
    }
}

// ---------------- Kernel 2: recurrent scan (R14, unchanged) -----------------
#define SJSEG 25
#define SCH   16                       // steps per chunk
#define SXQ   38                       // float4 per step (152 floats)
#define SXROWF4 (SCH * SXQ + 2)        // +32B pad
#define SCHUNK_F4 (SCH * SXQ)          // 608

__global__ void __launch_bounds__(128, 4) scan_kernel(
    const float* __restrict__ U, const float* __restrict__ bb,
    const float* __restrict__ Wd, const float* __restrict__ bd,
    const float* __restrict__ rdp, float* __restrict__ out)
{
    __shared__ __align__(16) float hm[3][64];   // [gate][slot]; slot=j+(j>=25)*7
    __shared__ float4 part1[64];                // s=1 partials {z,r,h,_}
    __shared__ float4 Xs[2 * SXROWF4];          // double-buffered X chunks
    __shared__ float  head[64];

    const int tid = threadIdx.x;
    const int u   = tid & 63;               // unit (active if < 50)
    const int s   = tid >> 6;               // j-half
    const int b   = blockIdx.x;             // one batch row
    const bool active = (u < NU);
    const bool fin    = (s == 0) && active; // finalizer for unit u
    const int rbase = s * 32;               // hm region base (128B aligned)
    const int slot  = u + ((u >= SJSEG) ? 7 : 0);

    for (int idx = tid; idx < 3 * 64; idx += 128)
        (&hm[0][0])[idx] = 0.f;

    // U slice in scalar registers: j = s*25 + jj
    float Uz[SJSEG], Ur[SJSEG], Uh[SJSEG];
    #pragma unroll
    for (int jj = 0; jj < SJSEG; ++jj) {
        int j = s * SJSEG + jj;
        float vz = 0.f, vr = 0.f, vh = 0.f;
        if (active) {
            vz = U[j * NC + u];
            vr = U[j * NC + NU + u];
            vh = U[j * NC + 2 * NU + u];
        }
        Uz[jj] = vz; Ur[jj] = vr; Uh[jj] = vh;
    }

    float br0 = 0.f, br1 = 0.f, br2 = 0.f, wdu = 0.f;
    float rdp0 = 0.f, rdp1 = 0.f, rdp2 = 0.f, h = 0.f;
    if (fin) {
        br0 = bb[NC + u]; br1 = bb[NC + NU + u]; br2 = bb[NC + 2 * NU + u];
        wdu = Wd[u];
        rdp0 = rdp[0 * (B_ * NU) + b * NU + u];
        rdp1 = rdp[1 * (B_ * NU) + b * NU + u];
        rdp2 = rdp[2 * (B_ * NU) + b * NU + u];
    }

    // ---- cp.async chunk loader (all 128 threads) ----
    const uint32_t xs_base = smem_u32(&Xs[0]);
    auto issue_chunk = [&](int c, int buf) {
        #pragma unroll
        for (int it = 0; it < 5; ++it) {
            int lin = it * 128 + tid;
            if (lin < SCHUNK_F4) {
                int tt = lin / SXQ;
                int q  = lin - tt * SXQ;
                const float* g = g_X + ((size_t)b * T_ + c * SCH + tt) * XP + q * 4;
                uint32_t dst = xs_base +
                    (uint32_t)(buf * SXROWF4 + tt * SXQ + q) * 16u;
                asm volatile("cp.async.cg.shared.global [%0], [%1], 16;"
                             :: "r"(dst), "l"(g) : "memory");
            }
        }
        asm volatile("cp.async.commit_group;" ::: "memory");
    };

    issue_chunk(0, 0);
    issue_chunk(1, 1);
    asm volatile("cp.async.wait_group 1;" ::: "memory");   // chunk 0 ready
    __syncthreads();

    const float* XsF = reinterpret_cast<const float*>(Xs);
    const int NCHUNK = T_ / SCH;   // 32
    for (int c = 0; c < NCHUNK; ++c) {
        const int buf = c & 1;
        const float* Xrow = XsF + (size_t)buf * (SXROWF4 * 4);

        #pragma unroll 2
        for (int tt = 0; tt < SCH; ++tt) {
            // phase A: split-K partials, scalar FFMA, broadcast LDS.128
            float az = 0.f, ar = 0.f, ah = 0.f;
            const float4* hz4 = reinterpret_cast<const float4*>(&hm[0][rbase]);
            const float4* hr4 = reinterpret_cast<const float4*>(&hm[1][rbase]);
            const float4* hh4 = reinterpret_cast<const float4*>(&hm[2][rbase]);
            #pragma unroll
            for (int i = 0; i < 6; ++i) {
                float4 vz = hz4[i], vr = hr4[i], vh = hh4[i];
                az = fmaf(vz.x, Uz[4*i+0], az); ar = fmaf(vr.x, Ur[4*i+0], ar);
                ah = fmaf(vh.x, Uh[4*i+0], ah);
                az = fmaf(vz.y, Uz[4*i+1], az); ar = fmaf(vr.y, Ur[4*i+1], ar);
                ah = fmaf(vh.y, Uh[4*i+1], ah);
                az = fmaf(vz.z, Uz[4*i+2], az); ar = fmaf(vr.z, Ur[4*i+2], ar);
                ah = fmaf(vh.z, Uh[4*i+2], ah);
                az = fmaf(vz.w, Uz[4*i+3], az); ar = fmaf(vr.w, Ur[4*i+3], ar);
                ah = fmaf(vh.w, Uh[4*i+3], ah);
            }
            az = fmaf(hm[0][rbase + 24], Uz[24], az);
            ar = fmaf(hm[1][rbase + 24], Ur[24], ar);
            ah = fmaf(hm[2][rbase + 24], Uh[24], ah);

            if (s) part1[u] = make_float4(az, ar, ah, 0.f);
            __syncthreads();

            // phase B: finalizers combine 2 partials, update h, broadcast
            if (fin) {
                float4 p = part1[u];
                float sz = az + p.x, sr = ar + p.y, sh = ah + p.z;
                const float* Xp = Xrow + tt * (SXQ * 4);
                float xz = Xp[u], xr = Xp[NU + u], xh = Xp[2 * NU + u];
                float z  = sigm(xz + sz + br0);
                float r  = sigm(xr + sr + br1);
                float th = tanh_fast(xh + r * (sh + br2));
                h = z * h + (1.f - z) * th;
                hm[0][slot] = h * rdp0;
                hm[1][slot] = h * rdp1;
                hm[2][slot] = h * rdp2;
            }
            __syncthreads();
        }

        // chunk boundary: refill consumed buffer with chunk c+2
        if (c + 2 < NCHUNK) {
            issue_chunk(c + 2, buf);
            asm volatile("cp.async.wait_group 1;" ::: "memory");  // c+1 ready
        } else {
            asm volatile("cp.async.wait_group 0;" ::: "memory");  // drain all
        }
        __syncthreads();
    }

    // dense head: out[b] = h . Wd + bd
    if (fin) head[u] = h * wdu;
    __syncthreads();
    if (tid == 0) {
        float sum = bd[0];
        for (int uu = 0; uu < NU; ++uu) sum += head[uu];
        out[b] = sum;
    }
}

// ---------------- launch ----------------
extern "C" void kernel_launch(void* const* d_in, const int* in_sizes, int n_in,
                              void* d_out, int out_size)
{
    const float* inp = (const float*)d_in[0];
    const float* W   = (const float*)d_in[1];
    const float* U   = (const float*)d_in[2];
    const float* bb  = (const float*)d_in[3];
    const float* Wd  = (const float*)d_in[4];
    const float* bd  = (const float*)d_in[5];
    const float* dp  = (const float*)d_in[6];
    const float* rdp = (const float*)d_in[7];
    float* out = (float*)d_out;

    cudaFuncSetAttribute(xproj_tc_kernel, cudaFuncAttributeMaxDynamicSharedMemorySize, SX_TOT);
    dim3 grid(B_, 2);
    xproj_tc_kernel<<<grid, 256, SX_TOT>>>(inp, W, bb, dp);
    scan_kernel<<<B_, 128>>>(U, bb, Wd, bd, rdp, out);
}

// round 17
// speedup vs baseline: 1.1819x; 1.0540x over previous
#include <cuda_runtime.h>
#include <cuda_bf16.h>
#include <cstdint>

#define B_  512
#define T_  512
#define F_  128
#define NU  50
#define NC  150   // 3*NU
#define XP  160   // padded X row (floats)

// Scratch for projected inputs X[b][t][160].
__device__ float g_X[(size_t)B_ * T_ * XP];

typedef unsigned long long ull;

__device__ __forceinline__ float sigm(float x) {
    return __fdividef(1.f, 1.f + __expf(-x));
}
__device__ __forceinline__ float tanh_fast(float x) {
    return __fdividef(2.f, 1.f + __expf(-2.f * x)) - 1.f;
}
__device__ __forceinline__ uint32_t smem_u32(const void* p) {
    uint32_t a;
    asm("{ .reg .u64 t; cvta.to.shared.u64 t, %1; cvt.u32.u64 %0, t; }"
        : "=r"(a) : "l"(p));
    return a;
}

// ---- cheap bf16 hi/lo split helpers ----
__device__ __forceinline__ float trunchi(float v) {
    return __uint_as_float(__float_as_uint(v) & 0xFFFF0000u);
}
__device__ __forceinline__ uint32_t prmt_hi(float a, float b) {
    uint32_t r;
    asm("prmt.b32 %0, %1, %2, 0x7632;"
        : "=r"(r) : "r"(__float_as_uint(a)), "r"(__float_as_uint(b)));
    return r;
}
__device__ __forceinline__ uint32_t bf2_rn(float lo, float hi_) {
    uint32_t r;
    asm("cvt.rn.bf16x2.f32 %0, %1, %2;" : "=r"(r) : "f"(hi_), "f"(lo));
    return r;
}

// ================= Kernel 1: xproj via HMMA (R16, unchanged) ================
#define TM   128
#define TNH  80                          // N per CTA
#define TK   128
#define LDAB 136                         // bf16 stride (272B, ldmatrix-friendly)

#define SX_BIAS 0                                   // 160 floats (global cols)
#define SX_BH   1024                                // 80*136*2 = 21760
#define SX_BL   (SX_BH + TNH * LDAB * 2)
#define SX_AH   (SX_BL + TNH * LDAB * 2)
#define SX_AL   (SX_AH + TM * LDAB * 2)
#define SX_TOT  (SX_AL + TM * LDAB * 2)             // 114176 (~111.5KB)

__device__ __forceinline__ void ldmx4(uint32_t* r, uint32_t addr) {
    asm volatile("ldmatrix.sync.aligned.m8n8.x4.shared.b16 {%0,%1,%2,%3}, [%4];"
                 : "=r"(r[0]), "=r"(r[1]), "=r"(r[2]), "=r"(r[3]) : "r"(addr));
}
__device__ __forceinline__ void mma16816(float* c, const uint32_t* a,
                                         uint32_t b0, uint32_t b1) {
    asm volatile(
        "mma.sync.aligned.m16n8k16.row.col.f32.bf16.bf16.f32 "
        "{%0,%1,%2,%3}, {%4,%5,%6,%7}, {%8,%9}, {%0,%1,%2,%3};"
        : "+f"(c[0]), "+f"(c[1]), "+f"(c[2]), "+f"(c[3])
        : "r"(a[0]), "r"(a[1]), "r"(a[2]), "r"(a[3]), "r"(b0), "r"(b1));
}

__global__ void __launch_bounds__(256, 2) xproj_tc_kernel(
    const float* __restrict__ inp, const float* __restrict__ W,
    const float* __restrict__ bb, const float* __restrict__ dp)
{
    extern __shared__ char smx[];
    const uint32_t sb = smem_u32(smx);
    const int b   = blockIdx.x;
    const int ny  = blockIdx.y;            // n-half: cols [ny*80, ny*80+80)
    const int n0g = ny * TNH;
    const int tid = threadIdx.x;
    const int wid = tid >> 5;
    const int lid = tid & 31;

    float* bias_s = reinterpret_cast<float*>(smx + SX_BIAS);
    for (int n = tid; n < XP; n += 256)
        bias_s[n] = (n < NC) ? bb[n] : 0.f;

    // Build B half = Weff^T rows [n0g, n0g+80) (hi/lo bf16), stride LDAB.
    {
        uint32_t* BH = reinterpret_cast<uint32_t*>(smx + SX_BH);
        uint32_t* BL = reinterpret_cast<uint32_t*>(smx + SX_BL);
        for (int i = tid; i < TNH * (TK / 2); i += 256) {
            int kp = i / TNH, n = i - kp * TNH;
            int ng = n0g + n;
            int k0 = 2 * kp;
            float w0 = 0.f, w1 = 0.f;
            if (ng < NC) {
                int g = ng / NU;
                w0 = W[k0 * NC + ng]       * dp[g * (B_ * F_) + b * F_ + k0];
                w1 = W[(k0 + 1) * NC + ng] * dp[g * (B_ * F_) + b * F_ + k0 + 1];
            }
            uint32_t off = (uint32_t)(n * (LDAB / 2) + kp);
            BH[off] = prmt_hi(w0, w1);
            BL[off] = bf2_rn(w0 - trunchi(w0), w1 - trunchi(w1));
        }
    }

    const int m0 = wid * 16;
    const uint32_t a_lane = (uint32_t)(((m0 + (lid & 15)) * LDAB + ((lid >> 4) << 3)) * 2);
    const uint32_t b_lane = (uint32_t)(((((lid & 7) + ((lid >> 4) << 3)) * LDAB) +
                                        (((lid >> 3) & 1) << 3)) * 2);
    const uint32_t ah_base = sb + SX_AH + a_lane;
    const uint32_t al_base = sb + SX_AL + a_lane;
    const uint32_t bh_base = sb + SX_BH + b_lane;
    const uint32_t bl_base = sb + SX_BL + b_lane;

    for (int tile = 0; tile < T_ / TM; ++tile) {
        const int t0 = tile * TM;
        __syncthreads();   // prev tile's ldmatrix done (covers B build on tile 0)

        // Stage A tile (hi/lo bf16): float4 loads, PRMT hi, dual-cvt lo, STS.64
        {
            uint2* AH2 = reinterpret_cast<uint2*>(smx + SX_AH);
            uint2* AL2 = reinterpret_cast<uint2*>(smx + SX_AL);
            const float4* src4 = reinterpret_cast<const float4*>(
                inp + ((size_t)b * T_ + t0) * F_);
            for (int i = tid; i < TM * (TK / 4); i += 256) {   // 4096
                int m = i >> 5, kq = i & 31;
                float4 v = src4[i];
                uint32_t h01 = prmt_hi(v.x, v.y);
                uint32_t h23 = prmt_hi(v.z, v.w);
                uint32_t l01 = bf2_rn(v.x - trunchi(v.x), v.y - trunchi(v.y));
                uint32_t l23 = bf2_rn(v.z - trunchi(v.z), v.w - trunchi(v.w));
                uint32_t o2 = (uint32_t)(m * (LDAB / 4) + kq);   // LDAB/4 = 34
                AH2[o2] = make_uint2(h01, h23);
                AL2[o2] = make_uint2(l01, l23);
            }
        }
        __syncthreads();

        float c[10][4];
        #pragma unroll
        for (int nb = 0; nb < 10; ++nb)
            #pragma unroll
            for (int q = 0; q < 4; ++q) c[nb][q] = 0.f;

        #pragma unroll
        for (int ks = 0; ks < 8; ++ks) {
            const uint32_t kb = (uint32_t)(ks * 32);
            uint32_t ah[4], al[4];
            ldmx4(ah, ah_base + kb);
            ldmx4(al, al_base + kb);
            #pragma unroll
            for (int p = 0; p < 5; ++p) {
                const uint32_t nboff = (uint32_t)(p * 16 * LDAB * 2) + kb;
                uint32_t bh[4], bl[4];
                ldmx4(bh, bh_base + nboff);
                ldmx4(bl, bl_base + nboff);
                mma16816(c[2 * p],     ah, bh[0], bh[1]);
                mma16816(c[2 * p],     ah, bl[0], bl[1]);
                mma16816(c[2 * p],     al, bh[0], bh[1]);
                mma16816(c[2 * p + 1], ah, bh[2], bh[3]);
                mma16816(c[2 * p + 1], ah, bl[2], bl[3]);
                mma16816(c[2 * p + 1], al, bh[2], bh[3]);
            }
        }

        const int rrow = m0 + (lid >> 2);
        const int ccol = (lid & 3) * 2;
        float* o0 = g_X + ((size_t)b * T_ + t0 + rrow) * XP;
        float* o1 = o0 + 8 * XP;
        #pragma unroll
        for (int nb = 0; nb < 10; ++nb) {
            int col = n0g + nb * 8 + ccol;
            float2 bz = *reinterpret_cast<const float2*>(bias_s + col);
            float2 v0 = make_float2(c[nb][0] + bz.x, c[nb][1] + bz.y);
            float2 v1 = make_float2(c[nb][2] + bz.x, c[nb][3] + bz.y);
            *reinterpret_cast<float2*>(o0 + col) = v0;
            *reinterpret_cast<float2*>(o1 + col) = v1;
        }
    }
}

// ---------------- Kernel 2: recurrent scan, one thread per (unit, gate) -----
// 512 CTAs x 1 batch row, 160 threads (5 warps): g = tid/50 (gate), u = tid%50.
// Each worker thread computes its gate's FULL 50-j dot product (no split-K):
// 50 FFMA in 2 sub-chains. Gates r,hh export their dot via ex[]; the z-thread
// (g==0) finalizes: activations, h update, hm broadcast. 2 barriers/step.
// X via cp.async double buffer (CH=16). 150/160 lanes useful.
#define SCH   16                       // steps per chunk
#define SXQ   38                       // float4 per step (152 floats)
#define SXROWF4 (SCH * SXQ + 2)        // +32B pad
#define SCHUNK_F4 (SCH * SXQ)          // 608

__global__ void __launch_bounds__(160, 4) scan_kernel(
    const float* __restrict__ U, const float* __restrict__ bb,
    const float* __restrict__ Wd, const float* __restrict__ bd,
    const float* __restrict__ rdp, float* __restrict__ out)
{
    __shared__ __align__(16) float hm[3][56];   // [gate][u]; row = 224B (16-mult)
    __shared__ float  ex[2][56];                // r,hh gate dots
    __shared__ float4 Xs[2 * SXROWF4];          // double-buffered X chunks
    __shared__ float  head[56];

    const int tid = threadIdx.x;
    const int g   = tid / NU;              // 0,1,2 worker gates; 3 = idle tail
    const int u   = tid - g * NU;
    const bool work = (tid < 3 * NU);      // 150 workers
    const bool fin  = (g == 0);            // z-gate thread finalizes unit u
    const int gg   = work ? g : 0;         // clamp for safe smem addressing
    const int b    = blockIdx.x;           // one batch row

    for (int idx = tid; idx < 3 * 56; idx += 160)
        (&hm[0][0])[idx] = 0.f;

    // U column for this (gate, unit): Ug[j] = U[j][g*50 + u]
    float Ug[NU];
    #pragma unroll
    for (int j = 0; j < NU; ++j)
        Ug[j] = work ? U[j * NC + g * NU + u] : 0.f;

    float brg = 0.f, br1 = 0.f, br2 = 0.f, wdu = 0.f;
    float rdp0 = 0.f, rdp1 = 0.f, rdp2 = 0.f, h = 0.f;
    if (fin) {
        brg = bb[NC + u]; br1 = bb[NC + NU + u]; br2 = bb[NC + 2 * NU + u];
        wdu = Wd[u];
        rdp0 = rdp[0 * (B_ * NU) + b * NU + u];
        rdp1 = rdp[1 * (B_ * NU) + b * NU + u];
        rdp2 = rdp[2 * (B_ * NU) + b * NU + u];
    }

    // ---- cp.async chunk loader (all 160 threads) ----
    const uint32_t xs_base = smem_u32(&Xs[0]);
    auto issue_chunk = [&](int c, int buf) {
        #pragma unroll
        for (int it = 0; it < 4; ++it) {
            int lin = it * 160 + tid;
            if (lin < SCHUNK_F4) {
                int tt = lin / SXQ;
                int q  = lin - tt * SXQ;
                const float* gm = g_X + ((size_t)b * T_ + c * SCH + tt) * XP + q * 4;
                uint32_t dst = xs_base +
                    (uint32_t)(buf * SXROWF4 + tt * SXQ + q) * 16u;
                asm volatile("cp.async.cg.shared.global [%0], [%1], 16;"
                             :: "r"(dst), "l"(gm) : "memory");
            }
        }
        asm volatile("cp.async.commit_group;" ::: "memory");
    };

    issue_chunk(0, 0);
    issue_chunk(1, 1);
    asm volatile("cp.async.wait_group 1;" ::: "memory");   // chunk 0 ready
    __syncthreads();

    const float* XsF = reinterpret_cast<const float*>(Xs);
    const int NCHUNK = T_ / SCH;   // 32
    for (int c = 0; c < NCHUNK; ++c) {
        const int buf = c & 1;
        const float* Xrow = XsF + (size_t)buf * (SXROWF4 * 4);

        #pragma unroll 2
        for (int tt = 0; tt < SCH; ++tt) {
            // phase A: full 50-j dot for this (u, gate); 2 sub-chains.
            float a0 = 0.f, a1 = 0.f;
            const float4* hv = reinterpret_cast<const float4*>(&hm[gg][0]);
            #pragma unroll
            for (int i = 0; i < 6; ++i) {
                float4 v = hv[i];
                a0 = fmaf(v.x, Ug[4*i+0], a0);
                a0 = fmaf(v.y, Ug[4*i+1], a0);
                a0 = fmaf(v.z, Ug[4*i+2], a0);
                a0 = fmaf(v.w, Ug[4*i+3], a0);
            }
            #pragma unroll
            for (int i = 6; i < 12; ++i) {
                float4 v = hv[i];
                a1 = fmaf(v.x, Ug[4*i+0], a1);
                a1 = fmaf(v.y, Ug[4*i+1], a1);
                a1 = fmaf(v.z, Ug[4*i+2], a1);
                a1 = fmaf(v.w, Ug[4*i+3], a1);
            }
            a0 = fmaf(hm[gg][48], Ug[48], a0);
            a1 = fmaf(hm[gg][49], Ug[49], a1);
            float dot = a0 + a1;

            if (work && !fin) ex[g - 1][u] = dot;
            __syncthreads();

            // phase B: z-gate thread finalizes unit u
            if (fin) {
                const float* Xp = Xrow + tt * (SXQ * 4);
                float xz = Xp[u], xr = Xp[NU + u], xh = Xp[2 * NU + u];
                float z  = sigm(xz + dot + brg);
                float r  = sigm(xr + ex[0][u] + br1);
                float th = tanh_fast(xh + r * (ex[1][u] + br2));
                h = z * h + (1.f - z) * th;
                hm[0][u] = h * rdp0;
                hm[1][u] = h * rdp1;
                hm[2][u] = h * rdp2;
            }
            __syncthreads();
        }

        // chunk boundary: refill consumed buffer with chunk c+2
        if (c + 2 < NCHUNK) {
            issue_chunk(c + 2, buf);
            asm volatile("cp.async.wait_group 1;" ::: "memory");  // c+1 ready
        } else {
            asm volatile("cp.async.wait_group 0;" ::: "memory");  // drain all
        }
        __syncthreads();
    }

    // dense head: out[b] = h . Wd + bd
    if (fin) head[u] = h * wdu;
    __syncthreads();
    if (tid == 0) {
        float sum = bd[0];
        for (int uu = 0; uu < NU; ++uu) sum += head[uu];
        out[b] = sum;
    }
}

// ---------------- launch ----------------
extern "C" void kernel_launch(void* const* d_in, const int* in_sizes, int n_in,
                              void* d_out, int out_size)
{
    const float* inp = (const float*)d_in[0];
    const float* W   = (const float*)d_in[1];
    const float* U   = (const float*)d_in[2];
    const float* bb  = (const float*)d_in[3];
    const float* Wd  = (const float*)d_in[4];
    const float* bd  = (const float*)d_in[5];
    const float* dp  = (const float*)d_in[6];
    const float* rdp = (const float*)d_in[7];
    float* out = (float*)d_out;

    cudaFuncSetAttribute(xproj_tc_kernel, cudaFuncAttributeMaxDynamicSharedMemorySize, SX_TOT);
    dim3 grid(B_, 2);
    xproj_tc_kernel<<<grid, 256, SX_TOT>>>(inp, W, bb, dp);
    scan_kernel<<<B_, 160>>>(U, bb, Wd, bd, rdp, out);
}